// round 14
// baseline (speedup 1.0000x reference)
#include <cuda_runtime.h>
#include <math.h>

#define NN 4096
#define KK 8
#define DD 512
#define HH 512
#define G4 2048
#define MAXLEV 4096
#define TM 32
#define BK2 16

// ---------------- static device scratch ----------------
__device__ __align__(16) float g_WlhhT[HH * G4];
__device__ __align__(16) float g_WrhhT[HH * G4];
__device__ __align__(16) float g_WlihT[DD * G4];
__device__ __align__(16) float g_WrihT[DD * G4];
__device__ __align__(16) float g_WencT[2 * HH * DD];
__device__ __align__(16) float g_biasL[G4];
__device__ __align__(16) float g_biasR[G4];
__device__ __align__(16) float g_AxL[NN * G4];
__device__ __align__(16) float g_AxR[NN * G4];
__device__ __align__(16) float g_AeL[NN * G4];
__device__ __align__(16) float g_AeR[NN * G4];
__device__ __align__(16) float g_h[2][2][NN * HH];   // [parity][side]
__device__ __align__(16) float g_c[2][NN * HH];      // [side]

// scheduling state
__device__ int g_chL[NN * 8], g_chR[NN * 8];
__device__ int g_lcnt[NN], g_rcnt[NN];
__device__ int g_lvl[NN];
__device__ int g_lvlCount[MAXLEV];
__device__ int g_lvlStart[MAXLEV + 1];
__device__ int g_cnt2L[MAXLEV * 9], g_cnt2R[MAXLEV * 9];
__device__ int g_cntL[MAXLEV * 10], g_cntR[MAXLEV * 10];
__device__ int g_curL[MAXLEV * 9], g_curR[MAXLEV * 9];
__device__ int g_orderL[NN], g_orderR[NN];
__device__ int g_maxK[MAXLEV];
__device__ int g_numLevels;
__device__ int g_barArrive;
__device__ int g_barGen;

// ---------------- helpers ----------------
__device__ __forceinline__ float sigf(float x) { return 1.0f / (1.0f + expf(-x)); }

__device__ __forceinline__ int ld_acquire(const int* p) {
    int v;
    asm volatile("ld.acquire.gpu.b32 %0, [%1];" : "=r"(v) : "l"(p) : "memory");
    return v;
}
__device__ __forceinline__ void st_release(int* p, int v) {
    asm volatile("st.release.gpu.b32 [%0], %1;" :: "l"(p), "r"(v) : "memory");
}

__device__ __forceinline__ void grid_bar() {
    __syncthreads();
    if (threadIdx.x == 0) {
        __threadfence();
        int gen = ld_acquire(&g_barGen);
        int a = atomicAdd(&g_barArrive, 1);
        if (a == (int)gridDim.x - 1) {
            g_barArrive = 0;
            __threadfence();
            st_release(&g_barGen, gen + 1);
        } else {
            while (ld_acquire(&g_barGen) == gen) { __nanosleep(32); }
        }
    }
    __syncthreads();
}

// ---------------- reset ----------------
__global__ void reset_kernel() {
    int idx = blockIdx.x * blockDim.x + threadIdx.x;
    int st = gridDim.x * blockDim.x;
    for (int i = idx; i < NN; i += st) g_lvl[i] = -1;
    for (int i = idx; i < MAXLEV; i += st) { g_lvlCount[i] = 0; g_maxK[i] = 0; }
    for (int i = idx; i < MAXLEV * 9; i += st) { g_cnt2L[i] = 0; g_cnt2R[i] = 0; }
    if (idx == 0) { g_barArrive = 0; g_barGen = 0; }
}

// ---------------- weight prep (transpose + gate interleave) ----------------
__global__ void prep_kernel(const float* __restrict__ Wl_ih, const float* __restrict__ Wl_hh,
                            const float* __restrict__ Wr_ih, const float* __restrict__ Wr_hh,
                            const float* __restrict__ bl_ih, const float* __restrict__ bl_hh,
                            const float* __restrict__ br_ih, const float* __restrict__ br_hh,
                            const float* __restrict__ W_enc) {
    int idx = blockIdx.x * blockDim.x + threadIdx.x;
    int z = blockIdx.y;
    if (z < 4) {
        if (idx < 512 * 2048) {
            int j = idx >> 11, col = idx & 2047;
            int e = col >> 2, g = col & 3;
            const float* src = (z == 0) ? Wl_hh : (z == 1) ? Wr_hh : (z == 2) ? Wl_ih : Wr_ih;
            float* dst = (z == 0) ? g_WlhhT : (z == 1) ? g_WrhhT : (z == 2) ? g_WlihT : g_WrihT;
            dst[idx] = src[(g * 512 + e) * 512 + j];
        }
    } else {
        if (idx < 1024 * 512) {
            int j = idx >> 9, e = idx & 511;
            g_WencT[idx] = W_enc[e * 1024 + j];
        }
        if (idx < 2048) {
            int e = idx >> 2, g = idx & 3;
            int r = g * 512 + e;
            g_biasL[idx] = bl_ih[r] + bl_hh[r];
            g_biasR[idx] = br_ih[r] + br_hh[r];
        }
    }
}

// ---------------- Ax = x0 @ WihT + bias ----------------
#define BM 128
#define BN 128
#define BK 8
__global__ __launch_bounds__(256) void gemm_ax(const float* __restrict__ x0) {
    int z = blockIdx.z;
    const float* B = z ? g_WrihT : g_WlihT;
    const float* bias = z ? g_biasR : g_biasL;
    float* C = z ? g_AxR : g_AxL;
    int n0 = blockIdx.x * BN;
    int m0 = blockIdx.y * BM;

    __shared__ float As[BK][BM + 4];
    __shared__ float Bs[BK][BN];

    float acc[8][8];
#pragma unroll
    for (int i = 0; i < 8; i++)
#pragma unroll
        for (int j = 0; j < 8; j++) acc[i][j] = 0.0f;

    int u = threadIdx.x;
    int tm = (u >> 4) * 8;
    int tn = (u & 15) * 8;

    for (int k0 = 0; k0 < 512; k0 += BK) {
        {
            int row = u >> 1, kk = (u & 1) * 4;
            float4 a4 = *(const float4*)&x0[(m0 + row) * 512 + k0 + kk];
            As[kk + 0][row] = a4.x; As[kk + 1][row] = a4.y;
            As[kk + 2][row] = a4.z; As[kk + 3][row] = a4.w;
        }
        {
            int kb = u >> 5, cc = (u & 31) * 4;
            *(float4*)&Bs[kb][cc] = *(const float4*)&B[(k0 + kb) * 2048 + n0 + cc];
        }
        __syncthreads();
#pragma unroll
        for (int k = 0; k < BK; k++) {
            float a[8], b[8];
            *(float4*)(a)     = *(float4*)&As[k][tm];
            *(float4*)(a + 4) = *(float4*)&As[k][tm + 4];
            *(float4*)(b)     = *(float4*)&Bs[k][tn];
            *(float4*)(b + 4) = *(float4*)&Bs[k][tn + 4];
#pragma unroll
            for (int i = 0; i < 8; i++)
#pragma unroll
                for (int j = 0; j < 8; j++) acc[i][j] += a[i] * b[j];
        }
        __syncthreads();
    }
#pragma unroll
    for (int i = 0; i < 8; i++) {
#pragma unroll
        for (int j = 0; j < 8; j += 4) {
            float4 o;
            o.x = acc[i][j + 0] + bias[n0 + tn + j + 0];
            o.y = acc[i][j + 1] + bias[n0 + tn + j + 1];
            o.z = acc[i][j + 2] + bias[n0 + tn + j + 2];
            o.w = acc[i][j + 3] + bias[n0 + tn + j + 3];
            *(float4*)&C[(m0 + tm + i) * 2048 + n0 + tn + j] = o;
        }
    }
}

// ---------------- step-0 state for all nodes, both sides ----------------
__global__ void init_state_kernel() {
    int idx = blockIdx.x * blockDim.x + threadIdx.x;
    int total = 2 * NN * 512;
    if (idx >= total) return;
    int side = idx / (NN * 512);
    int r = idx - side * (NN * 512);
    float4 g4 = ((const float4*)(side ? g_AxR : g_AxL))[r];
    float ig = sigf(g4.x);
    float gg = tanhf(g4.z);
    float oo = sigf(g4.w);
    float c0 = ig * gg;
    g_c[side][r] = c0;
    g_h[1][side][r] = oo * tanhf(c0);
}

// ---------------- scheduler (1 block) ----------------
__global__ void sched_kernel(const int* __restrict__ lch, const int* __restrict__ rch, int stride) {
    int tid = threadIdx.x;
    for (int idx = tid; idx < NN * 8; idx += 1024) {
        g_chL[idx] = lch[idx * stride];
        g_chR[idx] = rch[idx * stride];
    }
    __syncthreads();
    for (int i = tid; i < NN; i += 1024) {
        int cl = 0, cr = 0;
#pragma unroll
        for (int k = 0; k < 8; k++) {
            if (g_chL[i * 8 + k] >= 0) cl++;
            if (g_chR[i * 8 + k] >= 0) cr++;
        }
        g_lcnt[i] = cl; g_rcnt[i] = cr;
    }
    __syncthreads();

    volatile int* vl = g_lvl;
    __shared__ int sh_changed;
    for (int pass = 0; pass < NN; pass++) {
        if (tid == 0) sh_changed = 0;
        __syncthreads();
        for (int i = tid; i < NN; i += 1024) {
            if (vl[i] < 0) {
                int m = -1; bool ok = true;
#pragma unroll
                for (int k = 0; k < 8; k++) {
                    int c = g_chL[i * 8 + k];
                    if (c >= 0) { int lc = vl[c]; if (lc < 0) { ok = false; } else if (lc > m) m = lc; }
                    c = g_chR[i * 8 + k];
                    if (c >= 0) { int lc = vl[c]; if (lc < 0) { ok = false; } else if (lc > m) m = lc; }
                }
                if (ok) { vl[i] = m + 1; sh_changed = 1; }
            }
        }
        __syncthreads();
        if (!sh_changed) break;
    }

    __shared__ int sh_max;
    if (tid == 0) sh_max = 0;
    __syncthreads();
    for (int i = tid; i < NN; i += 1024) {
        int v = g_lvl[i];
        atomicMax(&sh_max, v);
        atomicAdd(&g_lvlCount[v], 1);
        atomicAdd(&g_cnt2L[v * 9 + g_lcnt[i]], 1);
        atomicAdd(&g_cnt2R[v * 9 + g_rcnt[i]], 1);
        int mk = g_lcnt[i] > g_rcnt[i] ? g_lcnt[i] : g_rcnt[i];
        atomicMax(&g_maxK[v], mk);
    }
    __syncthreads();
    int nl = sh_max + 1;
    if (tid == 0) {
        g_numLevels = nl;
        int s = 0;
        for (int v = 0; v < nl; v++) { g_lvlStart[v] = s; s += g_lvlCount[v]; }
        g_lvlStart[nl] = s;
    }
    __syncthreads();
    for (int v = tid; v < nl; v += 1024) {
        int ls = g_lvlStart[v];
        int s = 0;
        g_cntL[v * 10 + 9] = 0;
        for (int k = 8; k >= 0; k--) {
            g_curL[v * 9 + k] = ls + s;
            s += g_cnt2L[v * 9 + k];
            g_cntL[v * 10 + k] = s;
        }
        s = 0;
        g_cntR[v * 10 + 9] = 0;
        for (int k = 8; k >= 0; k--) {
            g_curR[v * 9 + k] = ls + s;
            s += g_cnt2R[v * 9 + k];
            g_cntR[v * 10 + k] = s;
        }
    }
    __syncthreads();
    for (int i = tid; i < NN; i += 1024) {
        int v = g_lvl[i];
        int p = atomicAdd(&g_curL[v * 9 + g_lcnt[i]], 1);
        g_orderL[p] = i;
        p = atomicAdd(&g_curR[v * 9 + g_rcnt[i]], 1);
        g_orderR[p] = i;
    }
}

// ---------------- persistent level-batched compute, small tiles ----------------
// Tile = [32 rows, 32 cols]; 256 threads; thread (m = tid>>3, nq = tid&7) owns
// one row and one float4 column group. K chunked by 16 through shared.
__global__ __launch_bounds__(256) void level_kernel(const float* __restrict__ b_enc,
                                                    float* __restrict__ out) {
    __shared__ float Ws[BK2][36];
    __shared__ float Hs[BK2][33];
    __shared__ const float* rowp[TM];
    __shared__ const float* rowp2[TM];
    __shared__ int s_ids[TM];
    __shared__ int s_child[TM];

    int tid = threadIdx.x;
    int m  = tid >> 3;
    int nq = tid & 7;
    int nb = gridDim.x;

    int numLev = g_numLevels;
    for (int v = 0; v < numLev; v++) {
        int base = g_lvlStart[v];
        int sz = g_lvlStart[v + 1] - base;
        int mk = g_maxK[v];

        // ---- chain steps ----
        for (int k = 1; k <= mk; k++) {
            int ML = g_cntL[v * 10 + k];
            int MR = g_cntR[v * 10 + k];
            int tL = ((ML + 31) >> 5) << 6;   // mblks * 64 nchunks
            int tR = ((MR + 31) >> 5) << 6;
            const float* hin0 = g_h[k & 1][0];
            const float* hin1 = g_h[k & 1][1];
            float* hout0 = g_h[(k + 1) & 1][0];
            float* hout1 = g_h[(k + 1) & 1][1];
            for (int t = blockIdx.x; t < tL + tR; t += nb) {
                int side = (t >= tL);
                int tt = side ? (t - tL) : t;
                int mblk = tt >> 6, nblk = tt & 63;
                int cnt = side ? MR : ML;
                const int* order = side ? g_orderR : g_orderL;
                const int* ch = side ? g_chR : g_chL;
                const float* W = side ? g_WrhhT : g_WlhhT;
                const float* hin = side ? hin1 : hin0;
                float* hout = side ? hout1 : hout0;
                float* cst = g_c[side];
                const float4* Aeq = (const float4*)(side ? g_AeR : g_AeL);

                __syncthreads();
                if (tid < TM) {
                    int mg = mblk * TM + tid;
                    int id = (mg < cnt) ? order[base + mg] : -1;
                    s_ids[tid] = id;
                    int cj = (id >= 0) ? ch[id * 8 + (k - 1)] : 0;
                    s_child[tid] = (cj < 0) ? 0 : cj;
                    rowp[tid] = hin + ((id >= 0) ? id : 0) * 512;
                }
                __syncthreads();

                int n0 = nblk * 32;
                float4 acc; acc.x = acc.y = acc.z = acc.w = 0.0f;
                for (int j0 = 0; j0 < 512; j0 += BK2) {
                    if (tid < 128) {
                        int jj = tid >> 3, c4 = (tid & 7) * 4;
                        *(float4*)&Ws[jj][c4] = *(const float4*)&W[(j0 + jj) * 2048 + n0 + c4];
                    } else {
                        int t2 = tid - 128;
                        int mm = t2 >> 2, jq = (t2 & 3) * 4;
                        float4 hv = *(const float4*)(rowp[mm] + j0 + jq);
                        Hs[jq + 0][mm] = hv.x; Hs[jq + 1][mm] = hv.y;
                        Hs[jq + 2][mm] = hv.z; Hs[jq + 3][mm] = hv.w;
                    }
                    __syncthreads();
#pragma unroll
                    for (int jj = 0; jj < BK2; jj++) {
                        float a = Hs[jj][m];
                        float4 b4 = *(float4*)&Ws[jj][nq * 4];
                        acc.x += a * b4.x; acc.y += a * b4.y;
                        acc.z += a * b4.z; acc.w += a * b4.w;
                    }
                    __syncthreads();
                }
                int id = s_ids[m];
                if (id >= 0) {
                    int e = nblk * 8 + nq;           // element index 0..511
                    float4 a4 = Aeq[s_child[m] * 512 + e];
                    float ig = sigf(acc.x + a4.x);
                    float ff = sigf(acc.y + a4.y);
                    float gg = tanhf(acc.z + a4.z);
                    float oo = sigf(acc.w + a4.w);
                    float cold = cst[id * 512 + e];
                    float cn = ff * cold + ig * gg;
                    cst[id * 512 + e] = cn;
                    hout[id * 512 + e] = oo * tanhf(cn);
                }
            }
            grid_bar();
        }

        // ---- encoder: enc = tanh([hl;hr] @ WencT + b_enc) ----
        {
            int tE = ((sz + 31) >> 5) << 4;   // mblks * 16 nchunks
            for (int t = blockIdx.x; t < tE; t += nb) {
                int mblk = t >> 4, nblk = t & 15;
                __syncthreads();
                if (tid < TM) {
                    int mg = mblk * TM + tid;
                    int id = (mg < sz) ? g_orderL[base + mg] : -1;
                    s_ids[tid] = id;
                    int iu = (id >= 0) ? id : 0;
                    int pL = (g_lcnt[iu] + 1) & 1;
                    int pR = (g_rcnt[iu] + 1) & 1;
                    rowp[tid]  = &g_h[pL][0][iu * 512];
                    rowp2[tid] = &g_h[pR][1][iu * 512];
                }
                __syncthreads();

                int n0 = nblk * 32;
                float4 acc; acc.x = acc.y = acc.z = acc.w = 0.0f;
                for (int j0 = 0; j0 < 1024; j0 += BK2) {
                    if (tid < 128) {
                        int jj = tid >> 3, c4 = (tid & 7) * 4;
                        *(float4*)&Ws[jj][c4] = *(const float4*)&g_WencT[(j0 + jj) * 512 + n0 + c4];
                    } else {
                        int t2 = tid - 128;
                        int mm = t2 >> 2, jq = (t2 & 3) * 4;
                        const float* rp = (j0 >= 512) ? rowp2[mm] : rowp[mm];
                        float4 hv = *(const float4*)(rp + (j0 & 511) + jq);
                        Hs[jq + 0][mm] = hv.x; Hs[jq + 1][mm] = hv.y;
                        Hs[jq + 2][mm] = hv.z; Hs[jq + 3][mm] = hv.w;
                    }
                    __syncthreads();
#pragma unroll
                    for (int jj = 0; jj < BK2; jj++) {
                        float a = Hs[jj][m];
                        float4 b4 = *(float4*)&Ws[jj][nq * 4];
                        acc.x += a * b4.x; acc.y += a * b4.y;
                        acc.z += a * b4.z; acc.w += a * b4.w;
                    }
                    __syncthreads();
                }
                int id = s_ids[m];
                if (id >= 0) {
                    int e0 = n0 + nq * 4;
                    float4 bv = *(const float4*)&b_enc[e0];
                    float4 o;
                    o.x = tanhf(acc.x + bv.x);
                    o.y = tanhf(acc.y + bv.y);
                    o.z = tanhf(acc.z + bv.z);
                    o.w = tanhf(acc.w + bv.w);
                    *(float4*)&out[id * 512 + e0] = o;
                }
            }
            grid_bar();
        }

        // ---- Ae = Wih @ enc + biases (both sides) ----
        {
            int tA = ((sz + 31) >> 5) << 6;
            for (int t = blockIdx.x; t < 2 * tA; t += nb) {
                int side = (t >= tA);
                int tt = side ? (t - tA) : t;
                int mblk = tt >> 6, nblk = tt & 63;
                const float* W = side ? g_WrihT : g_WlihT;
                const float4* biasq = (const float4*)(side ? g_biasR : g_biasL);
                float4* AeO = (float4*)(side ? g_AeR : g_AeL);

                __syncthreads();
                if (tid < TM) {
                    int mg = mblk * TM + tid;
                    int id = (mg < sz) ? g_orderL[base + mg] : -1;
                    s_ids[tid] = id;
                    rowp[tid] = out + ((id >= 0) ? id : 0) * 512;
                }
                __syncthreads();

                int n0 = nblk * 32;
                float4 acc; acc.x = acc.y = acc.z = acc.w = 0.0f;
                for (int j0 = 0; j0 < 512; j0 += BK2) {
                    if (tid < 128) {
                        int jj = tid >> 3, c4 = (tid & 7) * 4;
                        *(float4*)&Ws[jj][c4] = *(const float4*)&W[(j0 + jj) * 2048 + n0 + c4];
                    } else {
                        int t2 = tid - 128;
                        int mm = t2 >> 2, jq = (t2 & 3) * 4;
                        float4 hv = *(const float4*)(rowp[mm] + j0 + jq);
                        Hs[jq + 0][mm] = hv.x; Hs[jq + 1][mm] = hv.y;
                        Hs[jq + 2][mm] = hv.z; Hs[jq + 3][mm] = hv.w;
                    }
                    __syncthreads();
#pragma unroll
                    for (int jj = 0; jj < BK2; jj++) {
                        float a = Hs[jj][m];
                        float4 b4 = *(float4*)&Ws[jj][nq * 4];
                        acc.x += a * b4.x; acc.y += a * b4.y;
                        acc.z += a * b4.z; acc.w += a * b4.w;
                    }
                    __syncthreads();
                }
                int id = s_ids[m];
                if (id >= 0) {
                    int e = nblk * 8 + nq;
                    float4 b4 = biasq[e];
                    float4 o;
                    o.x = acc.x + b4.x;
                    o.y = acc.y + b4.y;
                    o.z = acc.z + b4.z;
                    o.w = acc.w + b4.w;
                    AeO[id * 512 + e] = o;
                }
            }
            grid_bar();
        }
    }
}

// ---------------- launch ----------------
extern "C" void kernel_launch(void* const* d_in, const int* in_sizes, int n_in,
                              void* d_out, int out_size) {
    const float* x0    = (const float*)d_in[0];
    const float* Wl_ih = (const float*)d_in[1];
    const float* Wl_hh = (const float*)d_in[2];
    const float* bl_ih = (const float*)d_in[3];
    const float* bl_hh = (const float*)d_in[4];
    const float* Wr_ih = (const float*)d_in[5];
    const float* Wr_hh = (const float*)d_in[6];
    const float* br_ih = (const float*)d_in[7];
    const float* br_hh = (const float*)d_in[8];
    const float* W_enc = (const float*)d_in[9];
    const float* b_enc = (const float*)d_in[10];
    const int*   lch   = (const int*)d_in[11];
    const int*   rch   = (const int*)d_in[12];
    float* out = (float*)d_out;

    int chstride = in_sizes[11] / (NN * KK);
    if (chstride < 1) chstride = 1;

    reset_kernel<<<256, 256>>>();

    dim3 pgrid((512 * 2048 + 255) / 256, 5);
    prep_kernel<<<pgrid, 256>>>(Wl_ih, Wl_hh, Wr_ih, Wr_hh,
                                bl_ih, bl_hh, br_ih, br_hh, W_enc);

    dim3 ggrid(2048 / BN, NN / BM, 2);
    gemm_ax<<<ggrid, 256>>>(x0);

    init_state_kernel<<<(2 * NN * 512 + 255) / 256, 256>>>();

    sched_kernel<<<1, 1024>>>(lch, rch, chstride);

    int sm = 148;
    cudaDeviceGetAttribute(&sm, cudaDevAttrMultiProcessorCount, 0);
    int occ = 0;
    cudaOccupancyMaxActiveBlocksPerMultiprocessor(&occ, level_kernel, 256, 0);
    if (occ < 1) occ = 1;
    if (occ > 2) occ = 2;
    int nb = sm * occ;
    level_kernel<<<nb, 256>>>(b_enc, out);
}

// round 16
// speedup vs baseline: 2.8793x; 2.8793x over previous
#include <cuda_runtime.h>
#include <math.h>

#define NN 4096
#define KK 8
#define DD 512
#define HH 512
#define G4 2048
#define MAXLEV 4096
#define TM 32

// ---------------- static device scratch ----------------
__device__ __align__(16) float g_WlhhT[HH * G4];
__device__ __align__(16) float g_WrhhT[HH * G4];
__device__ __align__(16) float g_WlihT[DD * G4];
__device__ __align__(16) float g_WrihT[DD * G4];
__device__ __align__(16) float g_WencT[2 * HH * DD];
__device__ __align__(16) float g_biasL[G4];
__device__ __align__(16) float g_biasR[G4];
__device__ __align__(16) float g_AxL[NN * G4];   // Ax before init_state; split-0 slab afterwards
__device__ __align__(16) float g_AxR[NN * G4];
__device__ __align__(16) float g_scr0[NN * G4];  // split-1 slabs
__device__ __align__(16) float g_scr1[NN * G4];
__device__ __align__(16) float g_AeL[NN * G4];
__device__ __align__(16) float g_AeR[NN * G4];
__device__ __align__(16) float g_h[2][2][NN * HH];   // [parity][side]
__device__ __align__(16) float g_c[2][NN * HH];      // [side]

// scheduling state
__device__ int g_chL[NN * 8], g_chR[NN * 8];
__device__ int g_lcnt[NN], g_rcnt[NN];
__device__ int g_lvl[NN];
__device__ int g_lvlCount[MAXLEV];
__device__ int g_lvlStart[MAXLEV + 1];
__device__ int g_cnt2L[MAXLEV * 9], g_cnt2R[MAXLEV * 9];
__device__ int g_cntL[MAXLEV * 10], g_cntR[MAXLEV * 10];
__device__ int g_curL[MAXLEV * 9], g_curR[MAXLEV * 9];
__device__ int g_orderL[NN], g_orderR[NN];
__device__ int g_maxK[MAXLEV];
__device__ int g_numLevels;
__device__ int g_barArrive;
__device__ int g_barGen;
__device__ int g_tcnt[4096];   // per-tile split counters

// ---------------- helpers ----------------
__device__ __forceinline__ float sigf(float x) { return 1.0f / (1.0f + expf(-x)); }

__device__ __forceinline__ int ld_acquire(const int* p) {
    int v;
    asm volatile("ld.acquire.gpu.b32 %0, [%1];" : "=r"(v) : "l"(p) : "memory");
    return v;
}
__device__ __forceinline__ void st_release(int* p, int v) {
    asm volatile("st.release.gpu.b32 [%0], %1;" :: "l"(p), "r"(v) : "memory");
}

__device__ __forceinline__ void grid_bar() {
    __syncthreads();
    if (threadIdx.x == 0) {
        __threadfence();
        int gen = ld_acquire(&g_barGen);
        int a = atomicAdd(&g_barArrive, 1);
        if (a == (int)gridDim.x - 1) {
            g_barArrive = 0;
            __threadfence();
            st_release(&g_barGen, gen + 1);
        } else {
            while (ld_acquire(&g_barGen) == gen) { __nanosleep(32); }
        }
    }
    __syncthreads();
}

// ---------------- reset ----------------
__global__ void reset_kernel() {
    int idx = blockIdx.x * blockDim.x + threadIdx.x;
    int st = gridDim.x * blockDim.x;
    for (int i = idx; i < NN; i += st) g_lvl[i] = -1;
    for (int i = idx; i < MAXLEV; i += st) { g_lvlCount[i] = 0; g_maxK[i] = 0; }
    for (int i = idx; i < MAXLEV * 9; i += st) { g_cnt2L[i] = 0; g_cnt2R[i] = 0; }
    for (int i = idx; i < 4096; i += st) g_tcnt[i] = 0;
    if (idx == 0) { g_barArrive = 0; g_barGen = 0; }
}

// ---------------- weight prep (transpose + gate interleave) ----------------
__global__ void prep_kernel(const float* __restrict__ Wl_ih, const float* __restrict__ Wl_hh,
                            const float* __restrict__ Wr_ih, const float* __restrict__ Wr_hh,
                            const float* __restrict__ bl_ih, const float* __restrict__ bl_hh,
                            const float* __restrict__ br_ih, const float* __restrict__ br_hh,
                            const float* __restrict__ W_enc) {
    int idx = blockIdx.x * blockDim.x + threadIdx.x;
    int z = blockIdx.y;
    if (z < 4) {
        if (idx < 512 * 2048) {
            int j = idx >> 11, col = idx & 2047;
            int e = col >> 2, g = col & 3;
            const float* src = (z == 0) ? Wl_hh : (z == 1) ? Wr_hh : (z == 2) ? Wl_ih : Wr_ih;
            float* dst = (z == 0) ? g_WlhhT : (z == 1) ? g_WrhhT : (z == 2) ? g_WlihT : g_WrihT;
            dst[idx] = src[(g * 512 + e) * 512 + j];
        }
    } else {
        if (idx < 1024 * 512) {
            int j = idx >> 9, e = idx & 511;
            g_WencT[idx] = W_enc[e * 1024 + j];
        }
        if (idx < 2048) {
            int e = idx >> 2, g = idx & 3;
            int r = g * 512 + e;
            g_biasL[idx] = bl_ih[r] + bl_hh[r];
            g_biasR[idx] = br_ih[r] + br_hh[r];
        }
    }
}

// ---------------- Ax = x0 @ WihT + bias ----------------
#define BM 128
#define BN 128
#define BK 8
__global__ __launch_bounds__(256) void gemm_ax(const float* __restrict__ x0) {
    int z = blockIdx.z;
    const float* B = z ? g_WrihT : g_WlihT;
    const float* bias = z ? g_biasR : g_biasL;
    float* C = z ? g_AxR : g_AxL;
    int n0 = blockIdx.x * BN;
    int m0 = blockIdx.y * BM;

    __shared__ float As[BK][BM + 4];
    __shared__ float Bs[BK][BN];

    float acc[8][8];
#pragma unroll
    for (int i = 0; i < 8; i++)
#pragma unroll
        for (int j = 0; j < 8; j++) acc[i][j] = 0.0f;

    int u = threadIdx.x;
    int tm = (u >> 4) * 8;
    int tn = (u & 15) * 8;

    for (int k0 = 0; k0 < 512; k0 += BK) {
        {
            int row = u >> 1, kk = (u & 1) * 4;
            float4 a4 = *(const float4*)&x0[(m0 + row) * 512 + k0 + kk];
            As[kk + 0][row] = a4.x; As[kk + 1][row] = a4.y;
            As[kk + 2][row] = a4.z; As[kk + 3][row] = a4.w;
        }
        {
            int kb = u >> 5, cc = (u & 31) * 4;
            *(float4*)&Bs[kb][cc] = *(const float4*)&B[(k0 + kb) * 2048 + n0 + cc];
        }
        __syncthreads();
#pragma unroll
        for (int k = 0; k < BK; k++) {
            float a[8], b[8];
            *(float4*)(a)     = *(float4*)&As[k][tm];
            *(float4*)(a + 4) = *(float4*)&As[k][tm + 4];
            *(float4*)(b)     = *(float4*)&Bs[k][tn];
            *(float4*)(b + 4) = *(float4*)&Bs[k][tn + 4];
#pragma unroll
            for (int i = 0; i < 8; i++)
#pragma unroll
                for (int j = 0; j < 8; j++) acc[i][j] += a[i] * b[j];
        }
        __syncthreads();
    }
#pragma unroll
    for (int i = 0; i < 8; i++) {
#pragma unroll
        for (int j = 0; j < 8; j += 4) {
            float4 o;
            o.x = acc[i][j + 0] + bias[n0 + tn + j + 0];
            o.y = acc[i][j + 1] + bias[n0 + tn + j + 1];
            o.z = acc[i][j + 2] + bias[n0 + tn + j + 2];
            o.w = acc[i][j + 3] + bias[n0 + tn + j + 3];
            *(float4*)&C[(m0 + tm + i) * 2048 + n0 + tn + j] = o;
        }
    }
}

// ---------------- step-0 state for all nodes, both sides ----------------
__global__ void init_state_kernel() {
    int idx = blockIdx.x * blockDim.x + threadIdx.x;
    int total = 2 * NN * 512;
    if (idx >= total) return;
    int side = idx / (NN * 512);
    int r = idx - side * (NN * 512);
    float4 g4 = ((const float4*)(side ? g_AxR : g_AxL))[r];
    float ig = sigf(g4.x);
    float gg = tanhf(g4.z);
    float oo = sigf(g4.w);
    float c0 = ig * gg;
    g_c[side][r] = c0;
    g_h[1][side][r] = oo * tanhf(c0);
}

// ---------------- scheduler (1 block) ----------------
__global__ void sched_kernel(const int* __restrict__ lch, const int* __restrict__ rch, int stride) {
    int tid = threadIdx.x;
    for (int idx = tid; idx < NN * 8; idx += 1024) {
        g_chL[idx] = lch[idx * stride];
        g_chR[idx] = rch[idx * stride];
    }
    __syncthreads();
    for (int i = tid; i < NN; i += 1024) {
        int cl = 0, cr = 0;
#pragma unroll
        for (int k = 0; k < 8; k++) {
            if (g_chL[i * 8 + k] >= 0) cl++;
            if (g_chR[i * 8 + k] >= 0) cr++;
        }
        g_lcnt[i] = cl; g_rcnt[i] = cr;
    }
    __syncthreads();

    volatile int* vl = g_lvl;
    __shared__ int sh_changed;
    for (int pass = 0; pass < NN; pass++) {
        if (tid == 0) sh_changed = 0;
        __syncthreads();
        for (int i = tid; i < NN; i += 1024) {
            if (vl[i] < 0) {
                int m = -1; bool ok = true;
#pragma unroll
                for (int k = 0; k < 8; k++) {
                    int c = g_chL[i * 8 + k];
                    if (c >= 0) { int lc = vl[c]; if (lc < 0) { ok = false; } else if (lc > m) m = lc; }
                    c = g_chR[i * 8 + k];
                    if (c >= 0) { int lc = vl[c]; if (lc < 0) { ok = false; } else if (lc > m) m = lc; }
                }
                if (ok) { vl[i] = m + 1; sh_changed = 1; }
            }
        }
        __syncthreads();
        if (!sh_changed) break;
    }

    __shared__ int sh_max;
    if (tid == 0) sh_max = 0;
    __syncthreads();
    for (int i = tid; i < NN; i += 1024) {
        int v = g_lvl[i];
        atomicMax(&sh_max, v);
        atomicAdd(&g_lvlCount[v], 1);
        atomicAdd(&g_cnt2L[v * 9 + g_lcnt[i]], 1);
        atomicAdd(&g_cnt2R[v * 9 + g_rcnt[i]], 1);
        int mk = g_lcnt[i] > g_rcnt[i] ? g_lcnt[i] : g_rcnt[i];
        atomicMax(&g_maxK[v], mk);
    }
    __syncthreads();
    int nl = sh_max + 1;
    if (tid == 0) {
        g_numLevels = nl;
        int s = 0;
        for (int v = 0; v < nl; v++) { g_lvlStart[v] = s; s += g_lvlCount[v]; }
        g_lvlStart[nl] = s;
    }
    __syncthreads();
    for (int v = tid; v < nl; v += 1024) {
        int ls = g_lvlStart[v];
        int s = 0;
        g_cntL[v * 10 + 9] = 0;
        for (int k = 8; k >= 0; k--) {
            g_curL[v * 9 + k] = ls + s;
            s += g_cnt2L[v * 9 + k];
            g_cntL[v * 10 + k] = s;
        }
        s = 0;
        g_cntR[v * 10 + 9] = 0;
        for (int k = 8; k >= 0; k--) {
            g_curR[v * 9 + k] = ls + s;
            s += g_cnt2R[v * 9 + k];
            g_cntR[v * 10 + k] = s;
        }
    }
    __syncthreads();
    for (int i = tid; i < NN; i += 1024) {
        int v = g_lvl[i];
        int p = atomicAdd(&g_curL[v * 9 + g_lcnt[i]], 1);
        g_orderL[p] = i;
        p = atomicAdd(&g_curR[v * 9 + g_rcnt[i]], 1);
        g_orderR[p] = i;
    }
}

// ---------------- double-buffered GEMM tile: [32 rows x 128 cols], K chunks of 32 ----------------
// 256 threads. Thread (ty=tid>>5, tx=tid&31) accumulates acc[4][4] for rows ty*4+.., col group tx.
__device__ __forceinline__ void gemm_tile(const float* __restrict__ W, int wld,
                                          int n0, int j0base, int nch,
                                          float acc[4][4],
                                          const float* const* rowp,
                                          float (*Ws)[128], float (*Hs)[36], int tid) {
    int tx = tid & 31, ty = tid >> 5;
    int mm = tid >> 3, jq = (tid & 7) * 4;
    float4 wreg[4]; float4 hreg;
    int j0 = j0base;
#pragma unroll
    for (int s = 0; s < 4; s++) {
        int slot = tid + 256 * s; int jj = slot >> 5, c4 = (slot & 31) * 4;
        wreg[s] = *(const float4*)&W[(j0 + jj) * wld + n0 + c4];
    }
    hreg = *(const float4*)(rowp[mm] + j0 + jq);
    for (int c = 0; c < nch; c++) {
        __syncthreads();
#pragma unroll
        for (int s = 0; s < 4; s++) {
            int slot = tid + 256 * s; int jj = slot >> 5, c4 = (slot & 31) * 4;
            *(float4*)&Ws[jj][c4] = wreg[s];
        }
        Hs[jq + 0][mm] = hreg.x; Hs[jq + 1][mm] = hreg.y;
        Hs[jq + 2][mm] = hreg.z; Hs[jq + 3][mm] = hreg.w;
        __syncthreads();
        if (c + 1 < nch) {
            j0 += 32;
#pragma unroll
            for (int s = 0; s < 4; s++) {
                int slot = tid + 256 * s; int jj = slot >> 5, c4 = (slot & 31) * 4;
                wreg[s] = *(const float4*)&W[(j0 + jj) * wld + n0 + c4];
            }
            hreg = *(const float4*)(rowp[mm] + j0 + jq);
        }
#pragma unroll
        for (int jj = 0; jj < 32; jj++) {
            float4 b4 = *(float4*)&Ws[jj][tx * 4];
            float4 a4 = *(float4*)&Hs[jj][ty * 4];
            acc[0][0] += a4.x * b4.x; acc[0][1] += a4.x * b4.y; acc[0][2] += a4.x * b4.z; acc[0][3] += a4.x * b4.w;
            acc[1][0] += a4.y * b4.x; acc[1][1] += a4.y * b4.y; acc[1][2] += a4.y * b4.z; acc[1][3] += a4.y * b4.w;
            acc[2][0] += a4.z * b4.x; acc[2][1] += a4.z * b4.y; acc[2][2] += a4.z * b4.z; acc[2][3] += a4.z * b4.w;
            acc[3][0] += a4.w * b4.x; acc[3][1] += a4.w * b4.y; acc[3][2] += a4.w * b4.z; acc[3][3] += a4.w * b4.w;
        }
    }
}

// store partial + counter; returns true if this block is the finisher
__device__ __forceinline__ int tile_commit(float acc[4][4], float* slab,
                                           const int* s_ids, int e, int cidx,
                                           int tid, int ty, int* s_old) {
    float4* slabq = (float4*)slab;
#pragma unroll
    for (int mi = 0; mi < 4; mi++) {
        int id = s_ids[ty * 4 + mi];
        if (id >= 0) {
            float4 o; o.x = acc[mi][0]; o.y = acc[mi][1]; o.z = acc[mi][2]; o.w = acc[mi][3];
            slabq[id * 512 + e] = o;
        }
    }
    __threadfence();
    __syncthreads();
    if (tid == 0) *s_old = atomicAdd(&g_tcnt[cidx], 1);
    __syncthreads();
    int fin = (*s_old == 1);
    if (fin && tid == 0) g_tcnt[cidx] = 0;
    return fin;
}

__device__ __forceinline__ float4 ldcg4(const float4* p) {
    float4 v;
    asm volatile("ld.global.cg.v4.f32 {%0,%1,%2,%3}, [%4];"
                 : "=f"(v.x), "=f"(v.y), "=f"(v.z), "=f"(v.w) : "l"(p));
    return v;
}

// ---------------- persistent level-batched compute ----------------
__global__ __launch_bounds__(256, 2) void level_kernel(const float* __restrict__ b_enc,
                                                       float* __restrict__ out) {
    __shared__ float Ws[32][128];
    __shared__ float Hs[32][36];
    __shared__ const float* rowp[TM];
    __shared__ int s_ids[TM];
    __shared__ int s_child[TM];
    __shared__ int s_old;

    int tid = threadIdx.x;
    int tx = tid & 31, ty = tid >> 5;
    int nb = gridDim.x;

    int numLev = g_numLevels;
    for (int v = 0; v < numLev; v++) {
        int base = g_lvlStart[v];
        int sz = g_lvlStart[v + 1] - base;
        int mk = g_maxK[v];
        int mblksAll = (sz + 31) >> 5;

        // ---- chain steps (split-K = 2, fused finisher) ----
        for (int k = 1; k <= mk; k++) {
            int ML = g_cntL[v * 10 + k];
            int MR = g_cntR[v * 10 + k];
            int tL = ((ML + 31) >> 5) << 4;
            int tR = ((MR + 31) >> 5) << 4;
            int TT = tL + tR;
            const float* hin0 = g_h[k & 1][0];
            const float* hin1 = g_h[k & 1][1];
            float* hout0 = g_h[(k + 1) & 1][0];
            float* hout1 = g_h[(k + 1) & 1][1];
            for (int t = blockIdx.x; t < 2 * TT; t += nb) {
                int spl = t & 1;
                int tt = t >> 1;
                int side = (tt >= tL);
                int ts = side ? (tt - tL) : tt;
                int mblk = ts >> 4, nblk = ts & 15;
                int cnt = side ? MR : ML;
                const int* order = side ? g_orderR : g_orderL;
                const int* ch = side ? g_chR : g_chL;
                const float* W = side ? g_WrhhT : g_WlhhT;
                const float* hin = side ? hin1 : hin0;
                float* hout = side ? hout1 : hout0;
                float* cst = g_c[side];
                const float4* Aeq = (const float4*)(side ? g_AeR : g_AeL);
                float* slabMine  = spl ? (side ? g_scr1 : g_scr0) : (side ? g_AxR : g_AxL);
                const float* slabOther = spl ? (side ? g_AxR : g_AxL) : (side ? g_scr1 : g_scr0);

                __syncthreads();
                if (tid < TM) {
                    int mg = mblk * TM + tid;
                    int id = (mg < cnt) ? order[base + mg] : -1;
                    s_ids[tid] = id;
                    int cj = (id >= 0) ? ch[id * 8 + (k - 1)] : 0;
                    s_child[tid] = (cj < 0) ? 0 : cj;
                    rowp[tid] = hin + ((id >= 0) ? id : 0) * 512;
                }
                __syncthreads();

                float acc[4][4];
#pragma unroll
                for (int a = 0; a < 4; a++)
#pragma unroll
                    for (int b = 0; b < 4; b++) acc[a][b] = 0.0f;

                int n0 = nblk * 128;
                gemm_tile(W, 2048, n0, spl * 256, 8, acc, rowp, Ws, Hs, tid);

                int e = (n0 >> 2) + tx;
                int cidx = side * 2048 + mblk * 16 + nblk;
                if (tile_commit(acc, slabMine, s_ids, e, cidx, tid, ty, &s_old)) {
                    const float4* oq = (const float4*)slabOther;
#pragma unroll
                    for (int mi = 0; mi < 4; mi++) {
                        int id = s_ids[ty * 4 + mi];
                        if (id < 0) continue;
                        float4 o4 = ldcg4(&oq[id * 512 + e]);
                        float4 a4 = Aeq[s_child[ty * 4 + mi] * 512 + e];
                        float ig = sigf(acc[mi][0] + o4.x + a4.x);
                        float ff = sigf(acc[mi][1] + o4.y + a4.y);
                        float gg = tanhf(acc[mi][2] + o4.z + a4.z);
                        float oo = sigf(acc[mi][3] + o4.w + a4.w);
                        float cold = cst[id * 512 + e];
                        float cn = ff * cold + ig * gg;
                        cst[id * 512 + e] = cn;
                        hout[id * 512 + e] = oo * tanhf(cn);
                    }
                }
            }
            grid_bar();
        }

        // ---- encoder: split by h-side (K 512 each), fused finisher ----
        {
            int TT = mblksAll * 4;          // N=512 -> 4 nblks
            for (int t = blockIdx.x; t < 2 * TT; t += nb) {
                int spl = t & 1;            // 0 = left h (Wenc rows 0..511), 1 = right
                int tt = t >> 1;
                int mblk = tt >> 2, nblk = tt & 3;

                __syncthreads();
                if (tid < TM) {
                    int mg = mblk * TM + tid;
                    int id = (mg < sz) ? g_orderL[base + mg] : -1;
                    s_ids[tid] = id;
                    int iu = (id >= 0) ? id : 0;
                    int par = ((spl ? g_rcnt[iu] : g_lcnt[iu]) + 1) & 1;
                    rowp[tid] = &g_h[par][spl][iu * 512];
                }
                __syncthreads();

                float acc[4][4];
#pragma unroll
                for (int a = 0; a < 4; a++)
#pragma unroll
                    for (int b = 0; b < 4; b++) acc[a][b] = 0.0f;

                int n0 = nblk * 128;
                gemm_tile(g_WencT + spl * 512 * 512, 512, n0, 0, 16, acc, rowp, Ws, Hs, tid);

                int e = (n0 >> 2) + tx;
                int cidx = mblk * 16 + nblk;
                float* slabMine = spl ? g_scr0 : g_AxL;
                const float* slabOther = spl ? g_AxL : g_scr0;
                if (tile_commit(acc, slabMine, s_ids, e, cidx, tid, ty, &s_old)) {
                    const float4* oq = (const float4*)slabOther;
                    float4 bv = *(const float4*)&b_enc[n0 + tx * 4];
#pragma unroll
                    for (int mi = 0; mi < 4; mi++) {
                        int id = s_ids[ty * 4 + mi];
                        if (id < 0) continue;
                        float4 o4 = ldcg4(&oq[id * 512 + e]);
                        float4 o;
                        o.x = tanhf(acc[mi][0] + o4.x + bv.x);
                        o.y = tanhf(acc[mi][1] + o4.y + bv.y);
                        o.z = tanhf(acc[mi][2] + o4.z + bv.z);
                        o.w = tanhf(acc[mi][3] + o4.w + bv.w);
                        *(float4*)&out[id * 512 + n0 + tx * 4] = o;
                    }
                }
            }
            grid_bar();
        }

        // ---- Ae = Wih @ enc + biases (both sides, split-K = 2, fused finisher) ----
        {
            int tS = mblksAll << 4;         // tiles per side
            int TT = 2 * tS;
            for (int t = blockIdx.x; t < 2 * TT; t += nb) {
                int spl = t & 1;
                int tt = t >> 1;
                int side = (tt >= tS);
                int ts = side ? (tt - tS) : tt;
                int mblk = ts >> 4, nblk = ts & 15;
                const float* W = side ? g_WrihT : g_WlihT;
                const float4* biasq = (const float4*)(side ? g_biasR : g_biasL);
                float4* AeO = (float4*)(side ? g_AeR : g_AeL);
                float* slabMine  = spl ? (side ? g_scr1 : g_scr0) : (side ? g_AxR : g_AxL);
                const float* slabOther = spl ? (side ? g_AxR : g_AxL) : (side ? g_scr1 : g_scr0);

                __syncthreads();
                if (tid < TM) {
                    int mg = mblk * TM + tid;
                    int id = (mg < sz) ? g_orderL[base + mg] : -1;
                    s_ids[tid] = id;
                    rowp[tid] = out + ((id >= 0) ? id : 0) * 512;
                }
                __syncthreads();

                float acc[4][4];
#pragma unroll
                for (int a = 0; a < 4; a++)
#pragma unroll
                    for (int b = 0; b < 4; b++) acc[a][b] = 0.0f;

                int n0 = nblk * 128;
                gemm_tile(W, 2048, n0, spl * 256, 8, acc, rowp, Ws, Hs, tid);

                int e = (n0 >> 2) + tx;
                int cidx = side * 2048 + mblk * 16 + nblk;
                if (tile_commit(acc, slabMine, s_ids, e, cidx, tid, ty, &s_old)) {
                    const float4* oq = (const float4*)slabOther;
                    float4 b4 = biasq[e];
#pragma unroll
                    for (int mi = 0; mi < 4; mi++) {
                        int id = s_ids[ty * 4 + mi];
                        if (id < 0) continue;
                        float4 o4 = ldcg4(&oq[id * 512 + e]);
                        float4 o;
                        o.x = acc[mi][0] + o4.x + b4.x;
                        o.y = acc[mi][1] + o4.y + b4.y;
                        o.z = acc[mi][2] + o4.z + b4.z;
                        o.w = acc[mi][3] + o4.w + b4.w;
                        AeO[id * 512 + e] = o;
                    }
                }
            }
            grid_bar();
        }
    }
}

// ---------------- launch ----------------
extern "C" void kernel_launch(void* const* d_in, const int* in_sizes, int n_in,
                              void* d_out, int out_size) {
    const float* x0    = (const float*)d_in[0];
    const float* Wl_ih = (const float*)d_in[1];
    const float* Wl_hh = (const float*)d_in[2];
    const float* bl_ih = (const float*)d_in[3];
    const float* bl_hh = (const float*)d_in[4];
    const float* Wr_ih = (const float*)d_in[5];
    const float* Wr_hh = (const float*)d_in[6];
    const float* br_ih = (const float*)d_in[7];
    const float* br_hh = (const float*)d_in[8];
    const float* W_enc = (const float*)d_in[9];
    const float* b_enc = (const float*)d_in[10];
    const int*   lch   = (const int*)d_in[11];
    const int*   rch   = (const int*)d_in[12];
    float* out = (float*)d_out;

    int chstride = in_sizes[11] / (NN * KK);
    if (chstride < 1) chstride = 1;

    reset_kernel<<<256, 256>>>();

    dim3 pgrid((512 * 2048 + 255) / 256, 5);
    prep_kernel<<<pgrid, 256>>>(Wl_ih, Wl_hh, Wr_ih, Wr_hh,
                                bl_ih, bl_hh, br_ih, br_hh, W_enc);

    dim3 ggrid(2048 / BN, NN / BM, 2);
    gemm_ax<<<ggrid, 256>>>(x0);

    init_state_kernel<<<(2 * NN * 512 + 255) / 256, 256>>>();

    sched_kernel<<<1, 1024>>>(lch, rch, chstride);

    int sm = 148;
    cudaDeviceGetAttribute(&sm, cudaDevAttrMultiProcessorCount, 0);
    int occ = 0;
    cudaOccupancyMaxActiveBlocksPerMultiprocessor(&occ, level_kernel, 256, 0);
    if (occ < 1) occ = 1;
    if (occ > 2) occ = 2;
    int nb = sm * occ;
    level_kernel<<<nb, 256>>>(b_enc, out);
}

// round 17
// speedup vs baseline: 2.9651x; 1.0298x over previous
#include <cuda_runtime.h>
#include <math.h>

#define NN 4096
#define KK 8
#define DD 512
#define HH 512
#define G4 2048
#define MAXLEV 4096
#define TM 32

typedef unsigned long long u64;

// ---------------- static device scratch ----------------
__device__ __align__(16) float g_WlhhT[HH * G4];
__device__ __align__(16) float g_WrhhT[HH * G4];
__device__ __align__(16) float g_WlihT[DD * G4];
__device__ __align__(16) float g_WrihT[DD * G4];
__device__ __align__(16) float g_WencT[2 * HH * DD];
__device__ __align__(16) float g_biasL[G4];
__device__ __align__(16) float g_biasR[G4];
__device__ __align__(16) float g_AxL[NN * G4];
__device__ __align__(16) float g_AxR[NN * G4];
__device__ __align__(16) float g_AeL[NN * G4];
__device__ __align__(16) float g_AeR[NN * G4];
__device__ __align__(16) float g_slab[8][NN * G4];   // split-K partial slabs
__device__ __align__(16) float g_h[2][2][NN * HH];   // [parity][side]
__device__ __align__(16) float g_c[2][NN * HH];      // [side]

// scheduling state
__device__ int g_chL[NN * 8], g_chR[NN * 8];
__device__ int g_lcnt[NN], g_rcnt[NN];
__device__ int g_lvl[NN];
__device__ int g_lvlCount[MAXLEV];
__device__ int g_lvlStart[MAXLEV + 1];
__device__ int g_cnt2L[MAXLEV * 9], g_cnt2R[MAXLEV * 9];
__device__ int g_cntL[MAXLEV * 10], g_cntR[MAXLEV * 10];
__device__ int g_curL[MAXLEV * 9], g_curR[MAXLEV * 9];
__device__ int g_orderL[NN], g_orderR[NN];
__device__ int g_maxK[MAXLEV];
__device__ int g_numLevels;
__device__ int g_barArrive;
__device__ int g_barGen;
__device__ int g_tcnt[4096];   // per-tile split counters

// ---------------- helpers ----------------
__device__ __forceinline__ float sigf(float x) { return 1.0f / (1.0f + expf(-x)); }

#define FMA2(acc, a, b) asm("fma.rn.f32x2 %0, %1, %2, %0;" : "+l"(acc) : "l"(a), "l"(b))

__device__ __forceinline__ float2 unpk(u64 v) {
    float2 r;
    asm("mov.b64 {%0,%1}, %2;" : "=f"(r.x), "=f"(r.y) : "l"(v));
    return r;
}

__device__ __forceinline__ int ld_acquire(const int* p) {
    int v;
    asm volatile("ld.acquire.gpu.b32 %0, [%1];" : "=r"(v) : "l"(p) : "memory");
    return v;
}
__device__ __forceinline__ void st_release(int* p, int v) {
    asm volatile("st.release.gpu.b32 [%0], %1;" :: "l"(p), "r"(v) : "memory");
}

__device__ __forceinline__ void grid_bar() {
    __syncthreads();
    if (threadIdx.x == 0) {
        __threadfence();
        int gen = ld_acquire(&g_barGen);
        int a = atomicAdd(&g_barArrive, 1);
        if (a == (int)gridDim.x - 1) {
            g_barArrive = 0;
            __threadfence();
            st_release(&g_barGen, gen + 1);
        } else {
            while (ld_acquire(&g_barGen) == gen) { __nanosleep(32); }
        }
    }
    __syncthreads();
}

__device__ __forceinline__ float4 ldcg4(const float4* p) {
    float4 v;
    asm volatile("ld.global.cg.v4.f32 {%0,%1,%2,%3}, [%4];"
                 : "=f"(v.x), "=f"(v.y), "=f"(v.z), "=f"(v.w) : "l"(p));
    return v;
}

// ---------------- reset ----------------
__global__ void reset_kernel() {
    int idx = blockIdx.x * blockDim.x + threadIdx.x;
    int st = gridDim.x * blockDim.x;
    for (int i = idx; i < NN; i += st) g_lvl[i] = -1;
    for (int i = idx; i < MAXLEV; i += st) { g_lvlCount[i] = 0; g_maxK[i] = 0; }
    for (int i = idx; i < MAXLEV * 9; i += st) { g_cnt2L[i] = 0; g_cnt2R[i] = 0; }
    for (int i = idx; i < 4096; i += st) g_tcnt[i] = 0;
    if (idx == 0) { g_barArrive = 0; g_barGen = 0; }
}

// ---------------- weight prep (transpose + gate interleave) ----------------
__global__ void prep_kernel(const float* __restrict__ Wl_ih, const float* __restrict__ Wl_hh,
                            const float* __restrict__ Wr_ih, const float* __restrict__ Wr_hh,
                            const float* __restrict__ bl_ih, const float* __restrict__ bl_hh,
                            const float* __restrict__ br_ih, const float* __restrict__ br_hh,
                            const float* __restrict__ W_enc) {
    int idx = blockIdx.x * blockDim.x + threadIdx.x;
    int z = blockIdx.y;
    if (z < 4) {
        if (idx < 512 * 2048) {
            int j = idx >> 11, col = idx & 2047;
            int e = col >> 2, g = col & 3;
            const float* src = (z == 0) ? Wl_hh : (z == 1) ? Wr_hh : (z == 2) ? Wl_ih : Wr_ih;
            float* dst = (z == 0) ? g_WlhhT : (z == 1) ? g_WrhhT : (z == 2) ? g_WlihT : g_WrihT;
            dst[idx] = src[(g * 512 + e) * 512 + j];
        }
    } else {
        if (idx < 1024 * 512) {
            int j = idx >> 9, e = idx & 511;
            g_WencT[idx] = W_enc[e * 1024 + j];
        }
        if (idx < 2048) {
            int e = idx >> 2, g = idx & 3;
            int r = g * 512 + e;
            g_biasL[idx] = bl_ih[r] + bl_hh[r];
            g_biasR[idx] = br_ih[r] + br_hh[r];
        }
    }
}

// ---------------- Ax = x0 @ WihT + bias ----------------
#define BM 128
#define BN 128
#define BK 8
__global__ __launch_bounds__(256) void gemm_ax(const float* __restrict__ x0) {
    int z = blockIdx.z;
    const float* B = z ? g_WrihT : g_WlihT;
    const float* bias = z ? g_biasR : g_biasL;
    float* C = z ? g_AxR : g_AxL;
    int n0 = blockIdx.x * BN;
    int m0 = blockIdx.y * BM;

    __shared__ float As[BK][BM + 4];
    __shared__ float Bs[BK][BN];

    float acc[8][8];
#pragma unroll
    for (int i = 0; i < 8; i++)
#pragma unroll
        for (int j = 0; j < 8; j++) acc[i][j] = 0.0f;

    int u = threadIdx.x;
    int tm = (u >> 4) * 8;
    int tn = (u & 15) * 8;

    for (int k0 = 0; k0 < 512; k0 += BK) {
        {
            int row = u >> 1, kk = (u & 1) * 4;
            float4 a4 = *(const float4*)&x0[(m0 + row) * 512 + k0 + kk];
            As[kk + 0][row] = a4.x; As[kk + 1][row] = a4.y;
            As[kk + 2][row] = a4.z; As[kk + 3][row] = a4.w;
        }
        {
            int kb = u >> 5, cc = (u & 31) * 4;
            *(float4*)&Bs[kb][cc] = *(const float4*)&B[(k0 + kb) * 2048 + n0 + cc];
        }
        __syncthreads();
#pragma unroll
        for (int k = 0; k < BK; k++) {
            float a[8], b[8];
            *(float4*)(a)     = *(float4*)&As[k][tm];
            *(float4*)(a + 4) = *(float4*)&As[k][tm + 4];
            *(float4*)(b)     = *(float4*)&Bs[k][tn];
            *(float4*)(b + 4) = *(float4*)&Bs[k][tn + 4];
#pragma unroll
            for (int i = 0; i < 8; i++)
#pragma unroll
                for (int j = 0; j < 8; j++) acc[i][j] += a[i] * b[j];
        }
        __syncthreads();
    }
#pragma unroll
    for (int i = 0; i < 8; i++) {
#pragma unroll
        for (int j = 0; j < 8; j += 4) {
            float4 o;
            o.x = acc[i][j + 0] + bias[n0 + tn + j + 0];
            o.y = acc[i][j + 1] + bias[n0 + tn + j + 1];
            o.z = acc[i][j + 2] + bias[n0 + tn + j + 2];
            o.w = acc[i][j + 3] + bias[n0 + tn + j + 3];
            *(float4*)&C[(m0 + tm + i) * 2048 + n0 + tn + j] = o;
        }
    }
}

// ---------------- step-0 state for all nodes, both sides ----------------
__global__ void init_state_kernel() {
    int idx = blockIdx.x * blockDim.x + threadIdx.x;
    int total = 2 * NN * 512;
    if (idx >= total) return;
    int side = idx / (NN * 512);
    int r = idx - side * (NN * 512);
    float4 g4 = ((const float4*)(side ? g_AxR : g_AxL))[r];
    float ig = sigf(g4.x);
    float gg = tanhf(g4.z);
    float oo = sigf(g4.w);
    float c0 = ig * gg;
    g_c[side][r] = c0;
    g_h[1][side][r] = oo * tanhf(c0);
}

// ---------------- scheduler (1 block) ----------------
__global__ void sched_kernel(const int* __restrict__ lch, const int* __restrict__ rch, int stride) {
    int tid = threadIdx.x;
    for (int idx = tid; idx < NN * 8; idx += 1024) {
        g_chL[idx] = lch[idx * stride];
        g_chR[idx] = rch[idx * stride];
    }
    __syncthreads();
    for (int i = tid; i < NN; i += 1024) {
        int cl = 0, cr = 0;
#pragma unroll
        for (int k = 0; k < 8; k++) {
            if (g_chL[i * 8 + k] >= 0) cl++;
            if (g_chR[i * 8 + k] >= 0) cr++;
        }
        g_lcnt[i] = cl; g_rcnt[i] = cr;
    }
    __syncthreads();

    volatile int* vl = g_lvl;
    __shared__ int sh_changed;
    for (int pass = 0; pass < NN; pass++) {
        if (tid == 0) sh_changed = 0;
        __syncthreads();
        for (int i = tid; i < NN; i += 1024) {
            if (vl[i] < 0) {
                int m = -1; bool ok = true;
#pragma unroll
                for (int k = 0; k < 8; k++) {
                    int c = g_chL[i * 8 + k];
                    if (c >= 0) { int lc = vl[c]; if (lc < 0) { ok = false; } else if (lc > m) m = lc; }
                    c = g_chR[i * 8 + k];
                    if (c >= 0) { int lc = vl[c]; if (lc < 0) { ok = false; } else if (lc > m) m = lc; }
                }
                if (ok) { vl[i] = m + 1; sh_changed = 1; }
            }
        }
        __syncthreads();
        if (!sh_changed) break;
    }

    __shared__ int sh_max;
    if (tid == 0) sh_max = 0;
    __syncthreads();
    for (int i = tid; i < NN; i += 1024) {
        int v = g_lvl[i];
        atomicMax(&sh_max, v);
        atomicAdd(&g_lvlCount[v], 1);
        atomicAdd(&g_cnt2L[v * 9 + g_lcnt[i]], 1);
        atomicAdd(&g_cnt2R[v * 9 + g_rcnt[i]], 1);
        int mk = g_lcnt[i] > g_rcnt[i] ? g_lcnt[i] : g_rcnt[i];
        atomicMax(&g_maxK[v], mk);
    }
    __syncthreads();
    int nl = sh_max + 1;
    if (tid == 0) {
        g_numLevels = nl;
        int s = 0;
        for (int v = 0; v < nl; v++) { g_lvlStart[v] = s; s += g_lvlCount[v]; }
        g_lvlStart[nl] = s;
    }
    __syncthreads();
    for (int v = tid; v < nl; v += 1024) {
        int ls = g_lvlStart[v];
        int s = 0;
        g_cntL[v * 10 + 9] = 0;
        for (int k = 8; k >= 0; k--) {
            g_curL[v * 9 + k] = ls + s;
            s += g_cnt2L[v * 9 + k];
            g_cntL[v * 10 + k] = s;
        }
        s = 0;
        g_cntR[v * 10 + 9] = 0;
        for (int k = 8; k >= 0; k--) {
            g_curR[v * 9 + k] = ls + s;
            s += g_cnt2R[v * 9 + k];
            g_cntR[v * 10 + k] = s;
        }
    }
    __syncthreads();
    for (int i = tid; i < NN; i += 1024) {
        int v = g_lvl[i];
        int p = atomicAdd(&g_curL[v * 9 + g_lcnt[i]], 1);
        g_orderL[p] = i;
        p = atomicAdd(&g_curR[v * 9 + g_rcnt[i]], 1);
        g_orderR[p] = i;
    }
}

// ---------------- f32x2 double-buffered GEMM tile: [32 x 128], K chunks of 32 ----------------
// 256 threads; thread (ty=tid>>5, tx=tid&31) owns rows ty*4+0..3, cols tx*4+0..3.
// Hs2 holds H values duplicated as (a,a) pairs -> broadcast operands via one LDS.128.
__device__ __forceinline__ void gemm_tile(const float* __restrict__ W, int wld,
                                          int n0, int j0base, int nch,
                                          u64 accp[4][2],
                                          const float* const* rowp,
                                          float (*Ws)[128], float (*Hs2)[68], int tid) {
    int tx = tid & 31, ty = tid >> 5;
    int mm = tid >> 3, jq = (tid & 7) * 4;
    float4 wreg[4]; float4 hreg;
    int j0 = j0base;
#pragma unroll
    for (int s = 0; s < 4; s++) {
        int slot = tid + 256 * s; int jj = slot >> 5, c4 = (slot & 31) * 4;
        wreg[s] = *(const float4*)&W[(j0 + jj) * wld + n0 + c4];
    }
    hreg = *(const float4*)(rowp[mm] + j0 + jq);
    for (int c = 0; c < nch; c++) {
        __syncthreads();
#pragma unroll
        for (int s = 0; s < 4; s++) {
            int slot = tid + 256 * s; int jj = slot >> 5, c4 = (slot & 31) * 4;
            *(float4*)&Ws[jj][c4] = wreg[s];
        }
        {
            float2 d0; d0.x = hreg.x; d0.y = hreg.x;
            float2 d1; d1.x = hreg.y; d1.y = hreg.y;
            float2 d2; d2.x = hreg.z; d2.y = hreg.z;
            float2 d3; d3.x = hreg.w; d3.y = hreg.w;
            *(float2*)&Hs2[jq + 0][2 * mm] = d0;
            *(float2*)&Hs2[jq + 1][2 * mm] = d1;
            *(float2*)&Hs2[jq + 2][2 * mm] = d2;
            *(float2*)&Hs2[jq + 3][2 * mm] = d3;
        }
        __syncthreads();
        if (c + 1 < nch) {
            j0 += 32;
#pragma unroll
            for (int s = 0; s < 4; s++) {
                int slot = tid + 256 * s; int jj = slot >> 5, c4 = (slot & 31) * 4;
                wreg[s] = *(const float4*)&W[(j0 + jj) * wld + n0 + c4];
            }
            hreg = *(const float4*)(rowp[mm] + j0 + jq);
        }
#pragma unroll
        for (int jj = 0; jj < 32; jj++) {
            ulonglong2 b  = *(const ulonglong2*)&Ws[jj][tx * 4];
            ulonglong2 aL = *(const ulonglong2*)&Hs2[jj][ty * 8];
            ulonglong2 aH = *(const ulonglong2*)&Hs2[jj][ty * 8 + 4];
            FMA2(accp[0][0], aL.x, b.x); FMA2(accp[0][1], aL.x, b.y);
            FMA2(accp[1][0], aL.y, b.x); FMA2(accp[1][1], aL.y, b.y);
            FMA2(accp[2][0], aH.x, b.x); FMA2(accp[2][1], aH.x, b.y);
            FMA2(accp[3][0], aH.y, b.x); FMA2(accp[3][1], aH.y, b.y);
        }
    }
}

__device__ __forceinline__ void acc_unpack(u64 accp[4][2], float acc[4][4]) {
#pragma unroll
    for (int mi = 0; mi < 4; mi++) {
        float2 lo = unpk(accp[mi][0]);
        float2 hi = unpk(accp[mi][1]);
        acc[mi][0] = lo.x; acc[mi][1] = lo.y; acc[mi][2] = hi.x; acc[mi][3] = hi.y;
    }
}

// store partial + counter; returns true if this block is the finisher (4-way)
__device__ __forceinline__ int tile_commit(float acc[4][4], float* slab,
                                           const int* s_ids, int e, int cidx,
                                           int tid, int ty, int* s_old) {
    float4* slabq = (float4*)slab;
#pragma unroll
    for (int mi = 0; mi < 4; mi++) {
        int id = s_ids[ty * 4 + mi];
        if (id >= 0) {
            float4 o; o.x = acc[mi][0]; o.y = acc[mi][1]; o.z = acc[mi][2]; o.w = acc[mi][3];
            slabq[id * 512 + e] = o;
        }
    }
    __threadfence();
    __syncthreads();
    if (tid == 0) *s_old = atomicAdd(&g_tcnt[cidx], 1);
    __syncthreads();
    int fin = (*s_old == 3);
    if (fin && tid == 0) g_tcnt[cidx] = 0;
    return fin;
}

// sum the 3 peer slabs' contribution for (id, e)
__device__ __forceinline__ float4 peer_sum(int sbase, int spl, int id, int e) {
    float4 s; s.x = s.y = s.z = s.w = 0.0f;
#pragma unroll
    for (int q = 1; q < 4; q++) {
        const float4* p = (const float4*)g_slab[sbase + ((spl + q) & 3)];
        float4 v = ldcg4(&p[id * 512 + e]);
        s.x += v.x; s.y += v.y; s.z += v.z; s.w += v.w;
    }
    return s;
}

// ---------------- persistent level-batched compute ----------------
__global__ __launch_bounds__(256, 2) void level_kernel(const float* __restrict__ b_enc,
                                                       float* __restrict__ out) {
    __shared__ float Ws[32][128];
    __shared__ float Hs2[32][68];
    __shared__ const float* rowp[TM];
    __shared__ int s_ids[TM];
    __shared__ int s_child[TM];
    __shared__ int s_old;

    int tid = threadIdx.x;
    int tx = tid & 31, ty = tid >> 5;
    int nb = gridDim.x;

    int numLev = g_numLevels;
    for (int v = 0; v < numLev; v++) {
        int base = g_lvlStart[v];
        int sz = g_lvlStart[v + 1] - base;
        int mk = g_maxK[v];
        int mblksAll = (sz + 31) >> 5;

        // ---- chain steps (split-K = 4, fused finisher) ----
        for (int k = 1; k <= mk; k++) {
            int ML = g_cntL[v * 10 + k];
            int MR = g_cntR[v * 10 + k];
            int tL = ((ML + 31) >> 5) << 4;
            int tR = ((MR + 31) >> 5) << 4;
            int TT = tL + tR;
            const float* hin0 = g_h[k & 1][0];
            const float* hin1 = g_h[k & 1][1];
            float* hout0 = g_h[(k + 1) & 1][0];
            float* hout1 = g_h[(k + 1) & 1][1];
            for (int t = blockIdx.x; t < 4 * TT; t += nb) {
                int spl = t & 3;
                int tt = t >> 2;
                int side = (tt >= tL);
                int ts = side ? (tt - tL) : tt;
                int mblk = ts >> 4, nblk = ts & 15;
                int cnt = side ? MR : ML;
                const int* order = side ? g_orderR : g_orderL;
                const int* ch = side ? g_chR : g_chL;
                const float* W = side ? g_WrhhT : g_WlhhT;
                const float* hin = side ? hin1 : hin0;
                float* hout = side ? hout1 : hout0;
                float* cst = g_c[side];
                const float4* Aeq = (const float4*)(side ? g_AeR : g_AeL);
                int sbase = side * 4;

                __syncthreads();
                if (tid < TM) {
                    int mg = mblk * TM + tid;
                    int id = (mg < cnt) ? order[base + mg] : -1;
                    s_ids[tid] = id;
                    int cj = (id >= 0) ? ch[id * 8 + (k - 1)] : 0;
                    s_child[tid] = (cj < 0) ? 0 : cj;
                    rowp[tid] = hin + ((id >= 0) ? id : 0) * 512;
                }
                __syncthreads();

                u64 accp[4][2] = {{0ULL,0ULL},{0ULL,0ULL},{0ULL,0ULL},{0ULL,0ULL}};
                int n0 = nblk * 128;
                gemm_tile(W, 2048, n0, spl * 128, 4, accp, rowp, Ws, Hs2, tid);
                float acc[4][4];
                acc_unpack(accp, acc);

                int e = (n0 >> 2) + tx;
                int cidx = side * 2048 + mblk * 16 + nblk;
                if (tile_commit(acc, g_slab[sbase + spl], s_ids, e, cidx, tid, ty, &s_old)) {
#pragma unroll
                    for (int mi = 0; mi < 4; mi++) {
                        int id = s_ids[ty * 4 + mi];
                        if (id < 0) continue;
                        float4 ps = peer_sum(sbase, spl, id, e);
                        float4 a4 = Aeq[s_child[ty * 4 + mi] * 512 + e];
                        float ig = sigf(acc[mi][0] + ps.x + a4.x);
                        float ff = sigf(acc[mi][1] + ps.y + a4.y);
                        float gg = tanhf(acc[mi][2] + ps.z + a4.z);
                        float oo = sigf(acc[mi][3] + ps.w + a4.w);
                        float cold = cst[id * 512 + e];
                        float cn = ff * cold + ig * gg;
                        cst[id * 512 + e] = cn;
                        hout[id * 512 + e] = oo * tanhf(cn);
                    }
                }
            }
            grid_bar();
        }

        // ---- encoder: K=1024 in 4 splits of 256, fused finisher ----
        {
            int TT = mblksAll * 4;          // N=512 -> 4 nblks
            for (int t = blockIdx.x; t < 4 * TT; t += nb) {
                int spl = t & 3;            // split: (spl>>1)=h-side, (spl&1)=k-half
                int tt = t >> 2;
                int mblk = tt >> 2, nblk = tt & 3;
                int hside = spl >> 1;

                __syncthreads();
                if (tid < TM) {
                    int mg = mblk * TM + tid;
                    int id = (mg < sz) ? g_orderL[base + mg] : -1;
                    s_ids[tid] = id;
                    int iu = (id >= 0) ? id : 0;
                    int par = ((hside ? g_rcnt[iu] : g_lcnt[iu]) + 1) & 1;
                    rowp[tid] = &g_h[par][hside][iu * 512];
                }
                __syncthreads();

                u64 accp[4][2] = {{0ULL,0ULL},{0ULL,0ULL},{0ULL,0ULL},{0ULL,0ULL}};
                int n0 = nblk * 128;
                gemm_tile(g_WencT + hside * 512 * 512, 512, n0, (spl & 1) * 256, 8,
                          accp, rowp, Ws, Hs2, tid);
                float acc[4][4];
                acc_unpack(accp, acc);

                int e = (n0 >> 2) + tx;
                int cidx = mblk * 4 + nblk;
                if (tile_commit(acc, g_slab[spl], s_ids, e, cidx, tid, ty, &s_old)) {
                    float4 bv = *(const float4*)&b_enc[n0 + tx * 4];
#pragma unroll
                    for (int mi = 0; mi < 4; mi++) {
                        int id = s_ids[ty * 4 + mi];
                        if (id < 0) continue;
                        float4 ps = peer_sum(0, spl, id, e);
                        float4 o;
                        o.x = tanhf(acc[mi][0] + ps.x + bv.x);
                        o.y = tanhf(acc[mi][1] + ps.y + bv.y);
                        o.z = tanhf(acc[mi][2] + ps.z + bv.z);
                        o.w = tanhf(acc[mi][3] + ps.w + bv.w);
                        *(float4*)&out[id * 512 + n0 + tx * 4] = o;
                    }
                }
            }
            grid_bar();
        }

        // ---- Ae = Wih @ enc + biases (both sides, split-K = 4, fused finisher) ----
        {
            int tS = mblksAll << 4;         // tiles per side (base)
            int TT = 2 * tS;
            for (int t = blockIdx.x; t < 4 * TT; t += nb) {
                int spl = t & 3;
                int tt = t >> 2;
                int side = (tt >= tS);
                int ts = side ? (tt - tS) : tt;
                int mblk = ts >> 4, nblk = ts & 15;
                const float* W = side ? g_WrihT : g_WlihT;
                const float4* biasq = (const float4*)(side ? g_biasR : g_biasL);
                float4* AeO = (float4*)(side ? g_AeR : g_AeL);
                int sbase = side * 4;

                __syncthreads();
                if (tid < TM) {
                    int mg = mblk * TM + tid;
                    int id = (mg < sz) ? g_orderL[base + mg] : -1;
                    s_ids[tid] = id;
                    rowp[tid] = out + ((id >= 0) ? id : 0) * 512;
                }
                __syncthreads();

                u64 accp[4][2] = {{0ULL,0ULL},{0ULL,0ULL},{0ULL,0ULL},{0ULL,0ULL}};
                int n0 = nblk * 128;
                gemm_tile(W, 2048, n0, spl * 128, 4, accp, rowp, Ws, Hs2, tid);
                float acc[4][4];
                acc_unpack(accp, acc);

                int e = (n0 >> 2) + tx;
                int cidx = side * 2048 + mblk * 16 + nblk;
                if (tile_commit(acc, g_slab[sbase + spl], s_ids, e, cidx, tid, ty, &s_old)) {
                    float4 b4 = biasq[e];
#pragma unroll
                    for (int mi = 0; mi < 4; mi++) {
                        int id = s_ids[ty * 4 + mi];
                        if (id < 0) continue;
                        float4 ps = peer_sum(sbase, spl, id, e);
                        float4 o;
                        o.x = acc[mi][0] + ps.x + b4.x;
                        o.y = acc[mi][1] + ps.y + b4.y;
                        o.z = acc[mi][2] + ps.z + b4.z;
                        o.w = acc[mi][3] + ps.w + b4.w;
                        AeO[id * 512 + e] = o;
                    }
                }
            }
            grid_bar();
        }
    }
}

// ---------------- launch ----------------
extern "C" void kernel_launch(void* const* d_in, const int* in_sizes, int n_in,
                              void* d_out, int out_size) {
    const float* x0    = (const float*)d_in[0];
    const float* Wl_ih = (const float*)d_in[1];
    const float* Wl_hh = (const float*)d_in[2];
    const float* bl_ih = (const float*)d_in[3];
    const float* bl_hh = (const float*)d_in[4];
    const float* Wr_ih = (const float*)d_in[5];
    const float* Wr_hh = (const float*)d_in[6];
    const float* br_ih = (const float*)d_in[7];
    const float* br_hh = (const float*)d_in[8];
    const float* W_enc = (const float*)d_in[9];
    const float* b_enc = (const float*)d_in[10];
    const int*   lch   = (const int*)d_in[11];
    const int*   rch   = (const int*)d_in[12];
    float* out = (float*)d_out;

    int chstride = in_sizes[11] / (NN * KK);
    if (chstride < 1) chstride = 1;

    reset_kernel<<<256, 256>>>();

    dim3 pgrid((512 * 2048 + 255) / 256, 5);
    prep_kernel<<<pgrid, 256>>>(Wl_ih, Wl_hh, Wr_ih, Wr_hh,
                                bl_ih, bl_hh, br_ih, br_hh, W_enc);

    dim3 ggrid(2048 / BN, NN / BM, 2);
    gemm_ax<<<ggrid, 256>>>(x0);

    init_state_kernel<<<(2 * NN * 512 + 255) / 256, 256>>>();

    sched_kernel<<<1, 1024>>>(lch, rch, chstride);

    int sm = 148;
    cudaDeviceGetAttribute(&sm, cudaDevAttrMultiProcessorCount, 0);
    int occ = 0;
    cudaOccupancyMaxActiveBlocksPerMultiprocessor(&occ, level_kernel, 256, 0);
    if (occ < 1) occ = 1;
    if (occ > 2) occ = 2;
    int nb = sm * occ;
    level_kernel<<<nb, 256>>>(b_enc, out);
}